// round 16
// baseline (speedup 1.0000x reference)
#include <cuda_runtime.h>
#include <cuda_fp16.h>
#include <cstdint>
#include <math.h>

#define NV 8192
#define DV 256

// ---------------- device scratch (allocation-free rule) ----------------
__device__ __half   g_WhT16[DV * NV];   // Wh^T fp16 [col][j], PERMUTED within 64-chunks
__device__ float    g_wa[DV];           // W @ a
__device__ float    g_u[NV];            // exp(f)
__device__ float    g_v[NV];            // exp(0.2 f)
__device__ float    g_c[NV];            // u/s
__device__ float    g_d[NV];            // v/s
__device__ unsigned g_bm[NV * 256];     // adjacency bitmask
__device__ float    g_part[2 * NV * DV];
__device__ float    g_elu_scratch[NV * DV];

__device__ __forceinline__ float elu_f(float x) { return x > 0.f ? x : expm1f(x); }
__device__ __forceinline__ uint32_t tf32r(float x) {
    uint32_t r; asm("cvt.rna.tf32.f32 %0, %1;" : "=r"(r) : "f"(x)); return r;
}
__device__ __forceinline__ void mma_tf32(float* d, const uint32_t* a, const uint32_t* b) {
    asm volatile("mma.sync.aligned.m16n8k8.row.col.f32.tf32.tf32.f32 "
        "{%0,%1,%2,%3},{%4,%5,%6,%7},{%8,%9},{%0,%1,%2,%3};"
        : "+f"(d[0]), "+f"(d[1]), "+f"(d[2]), "+f"(d[3])
        : "r"(a[0]), "r"(a[1]), "r"(a[2]), "r"(a[3]), "r"(b[0]), "r"(b[1]));
}
__device__ __forceinline__ void mma_f16(float* d, const uint32_t* a, const uint32_t* b) {
    asm volatile("mma.sync.aligned.m16n8k16.row.col.f32.f16.f16.f32 "
        "{%0,%1,%2,%3},{%4,%5,%6,%7},{%8,%9},{%0,%1,%2,%3};"
        : "+f"(d[0]), "+f"(d[1]), "+f"(d[2]), "+f"(d[3])
        : "r"(a[0]), "r"(a[1]), "r"(a[2]), "r"(a[3]), "r"(b[0]), "r"(b[1]));
}
__device__ __forceinline__ uint32_t smem_u32(const void* p) {
    uint32_t a;
    asm("{ .reg .u64 t; cvta.to.shared.u64 t, %1; cvt.u32.u64 %0, t; }" : "=r"(a) : "l"(p));
    return a;
}
__device__ __forceinline__ void cp_async16(uint32_t dst, const void* src) {
    asm volatile("cp.async.ca.shared.global [%0], [%1], 16;" :: "r"(dst), "l"(src));
}
#define CP_COMMIT() asm volatile("cp.async.commit_group;" ::: "memory")
#define CP_WAIT0()  asm volatile("cp.async.wait_group 0;" ::: "memory")
__device__ __forceinline__ uint32_t h2pack(float lo, float hi) {
    __half2 h = __floats2half2_rn(lo, hi);
    return *reinterpret_cast<uint32_t*>(&h);
}
// permute half-index j within its 64-half chunk: word t -> t<4 ? 2t : 2(t-4)+1
__device__ __forceinline__ int permj(int j) {
    int w = (j >> 1) & 31;
    int t = w & 7;
    int tp = (t < 4) ? (2 * t) : (2 * (t - 4) + 1);
    return (j & ~63) | (((w & 24) | tp) << 1) | (j & 1);
}

// ---------------------------------------------------------------------------
// Kernel 1: Wh = h @ W via tf32 mma; epilogue writes fp16 Wh^T [col][permj(j)].
// Also computes wa = W@a in block (0,0). CTA = 128 x 128 (grid 64x2).
// ---------------------------------------------------------------------------
#define WH_SMEM (128 * 36 * 4 + 32 * 136 * 4)
__global__ __launch_bounds__(512) void k_wh_mma(const float* __restrict__ h,
                                                const float* __restrict__ W,
                                                const float* __restrict__ a) {
    extern __shared__ char sm[];
    uint32_t* sA = (uint32_t*)sm;
    float*    sB = (float*)(sm + 128 * 36 * 4);
    const int tid = threadIdx.x;
    const int wid = tid >> 5, lane = tid & 31;
    const int wm = wid >> 2, wn = wid & 3;
    const int r0 = blockIdx.x * 128;
    const int cb = blockIdx.y * 128;
    const int br = tid >> 2, kq = (tid & 3) * 8;

    if (blockIdx.x == 0 && blockIdx.y == 0 && tid < 256) {
        const float4* W4 = (const float4*)W;
        const float4* a4 = (const float4*)a;
        float s = 0.f;
#pragma unroll 8
        for (int j = 0; j < 64; j++) {
            float4 w = __ldg(&W4[tid * 64 + j]);
            float4 av = __ldg(&a4[j]);
            s += w.x * av.x + w.y * av.y + w.z * av.z + w.w * av.w;
        }
        g_wa[tid] = s;
    }

    float acc[2][4][4];
#pragma unroll
    for (int mt = 0; mt < 2; mt++)
#pragma unroll
        for (int nb = 0; nb < 4; nb++)
#pragma unroll
            for (int q = 0; q < 4; q++) acc[mt][nb][q] = 0.f;

    for (int c = 0; c < 8; c++) {
        const int kb = c * 32;
        {
            float4 h0 = __ldg((const float4*)&h[(size_t)(r0 + br) * DV + kb + kq]);
            float4 h1 = __ldg((const float4*)&h[(size_t)(r0 + br) * DV + kb + kq + 4]);
            *(uint4*)&sA[br * 36 + kq]     = make_uint4(tf32r(h0.x), tf32r(h0.y), tf32r(h0.z), tf32r(h0.w));
            *(uint4*)&sA[br * 36 + kq + 4] = make_uint4(tf32r(h1.x), tf32r(h1.y), tf32r(h1.z), tf32r(h1.w));
        }
#pragma unroll
        for (int q = 0; q < 2; q++) {
            int idx = q * 512 + tid;
            int row = idx >> 5, col = (idx & 31) << 2;
            float4 w = __ldg((const float4*)&W[(size_t)(kb + row) * DV + cb + col]);
            float4 t;
            t.x = __uint_as_float(tf32r(w.x)); t.y = __uint_as_float(tf32r(w.y));
            t.z = __uint_as_float(tf32r(w.z)); t.w = __uint_as_float(tf32r(w.w));
            *(float4*)&sB[row * 136 + col] = t;
        }
        __syncthreads();
#pragma unroll
        for (int kk = 0; kk < 4; kk++) {
            uint32_t afr[2][4];
#pragma unroll
            for (int mt = 0; mt < 2; mt++) {
                int r = wm * 32 + mt * 16 + (lane >> 2);
                int cc = kk * 8 + (lane & 3);
                afr[mt][0] = sA[r * 36 + cc];
                afr[mt][1] = sA[(r + 8) * 36 + cc];
                afr[mt][2] = sA[r * 36 + cc + 4];
                afr[mt][3] = sA[(r + 8) * 36 + cc + 4];
            }
#pragma unroll
            for (int nb = 0; nb < 4; nb++) {
                uint32_t bfr[2];
                int kr = kk * 8 + (lane & 3);
                int nc = wn * 32 + nb * 8 + (lane >> 2);
                bfr[0] = __float_as_uint(sB[kr * 136 + nc]);
                bfr[1] = __float_as_uint(sB[(kr + 4) * 136 + nc]);
                mma_tf32(acc[0][nb], afr[0], bfr);
                mma_tf32(acc[1][nb], afr[1], bfr);
            }
        }
        __syncthreads();
    }
    // epilogue: fp16 Wh^T [col][permj(j)]
#pragma unroll
    for (int mt = 0; mt < 2; mt++)
#pragma unroll
        for (int nb = 0; nb < 4; nb++) {
            int gr = r0 + wm * 32 + mt * 16 + (lane >> 2);
            int cl = cb + wn * 32 + nb * 8 + (lane & 3) * 2;
            g_WhT16[(size_t)cl * NV + permj(gr)]           = __float2half_rn(acc[mt][nb][0]);
            g_WhT16[(size_t)(cl + 1) * NV + permj(gr)]     = __float2half_rn(acc[mt][nb][1]);
            g_WhT16[(size_t)cl * NV + permj(gr + 8)]       = __float2half_rn(acc[mt][nb][2]);
            g_WhT16[(size_t)(cl + 1) * NV + permj(gr + 8)] = __float2half_rn(acc[mt][nb][3]);
        }
}

// ---------------------------------------------------------------------------
// Kernel 2: f = h @ wa (exact); u = exp(f), v = exp(0.2 f)
// ---------------------------------------------------------------------------
__global__ __launch_bounds__(256) void k_f(const float* __restrict__ h) {
    const int wid = threadIdx.x >> 5, lane = threadIdx.x & 31;
    const int row = blockIdx.x * 8 + wid;
    float s = 0.f;
#pragma unroll
    for (int i = 0; i < 2; i++) {
        float4 w = __ldg((const float4*)&h[(size_t)row * DV + lane * 8 + i * 4]);
        float4 av = __ldg((const float4*)&g_wa[lane * 8 + i * 4]);
        s += w.x * av.x + w.y * av.y + w.z * av.z + w.w * av.w;
    }
#pragma unroll
    for (int m = 16; m; m >>= 1) s += __shfl_xor_sync(0xffffffffu, s, m);
    if (lane == 0) {
        g_u[row] = __expf(s);
        g_v[row] = __expf(0.2f * s);
    }
}

// ---------------------------------------------------------------------------
// Kernel 3: bitmask + rowsum (separable). One block per row.
// ---------------------------------------------------------------------------
__global__ __launch_bounds__(256) void k_prep(const int* __restrict__ adj) {
    const int row = blockIdx.x;
    const int wid = threadIdx.x >> 5, lane = threadIdx.x & 31;
    const float ui = __ldg(&g_u[row]);
    const float vi = __ldg(&g_v[row]);
    const float th = 1.f / ui;
    const int4* ar = (const int4*)(adj + (size_t)row * NV);
    const float4* u4p = (const float4*)g_u;
    const float4* v4p = (const float4*)g_v;

    float su = 0.f, sv = 0.f;
#pragma unroll
    for (int it = 0; it < 8; it++) {
        int idx4 = wid * 256 + it * 32 + lane;
        int4   ad = __ldg(&ar[idx4]);
        float4 u4 = __ldg(&u4p[idx4]);
        float4 v4 = __ldg(&v4p[idx4]);
        bool m0 = ad.x > 0, m1 = ad.y > 0, m2 = ad.z > 0, m3 = ad.w > 0;
        uint32_t nib = (m0 ? 1u : 0u) | (m1 ? 2u : 0u) | (m2 ? 4u : 0u) | (m3 ? 8u : 0u);
        bool p0 = u4.x > th, p1 = u4.y > th, p2 = u4.z > th, p3 = u4.w > th;
        su += (m0 && p0) ? u4.x : 0.f;  sv += (m0 && !p0) ? v4.x : 0.f;
        su += (m1 && p1) ? u4.y : 0.f;  sv += (m1 && !p1) ? v4.y : 0.f;
        su += (m2 && p2) ? u4.z : 0.f;  sv += (m2 && !p2) ? v4.z : 0.f;
        su += (m3 && p3) ? u4.w : 0.f;  sv += (m3 && !p3) ? v4.w : 0.f;
        uint32_t o = __shfl_xor_sync(0xffffffffu, nib, 1);
        uint32_t byt = (lane & 1) ? (o | (nib << 4)) : (nib | (o << 4));
        o = __shfl_xor_sync(0xffffffffu, byt, 2);
        uint32_t hlf = (lane & 2) ? (o | (byt << 8)) : (byt | (o << 8));
        o = __shfl_xor_sync(0xffffffffu, hlf, 4);
        uint32_t wrd = (lane & 4) ? (o | (hlf << 16)) : (hlf | (o << 16));
        if ((lane & 7) == 0)
            g_bm[(size_t)row * 256 + wid * 32 + it * 4 + (lane >> 3)] = wrd;
    }
#pragma unroll
    for (int m = 16; m; m >>= 1) {
        su += __shfl_xor_sync(0xffffffffu, su, m);
        sv += __shfl_xor_sync(0xffffffffu, sv, m);
    }
    __shared__ float ssu[8], ssv[8];
    if (lane == 0) { ssu[wid] = su; ssv[wid] = sv; }
    __syncthreads();
    if (threadIdx.x == 0) {
        float tu = 0.f, tv = 0.f;
#pragma unroll
        for (int i = 0; i < 8; i++) { tu += ssu[i]; tv += ssv[i]; }
        float s = ui * tu + vi * tv;
        g_c[row] = ui / s;
        g_d[row] = vi / s;
    }
}

// ---------------------------------------------------------------------------
// Kernel 4: h' = alpha @ Wh via fp16 m16n8k16. K=64/barrier, 64 iters.
// Paired-word (permuted) tiles, pitch 40 -> all fragment feeds are LDS.64,
// conflict-free. 512 threads, 16 warps (4x4), warp tile 32x64, split-K=2.
// ---------------------------------------------------------------------------
#define AT_U   0
#define AT_V   (AT_U + NV * 4)                 // 32 KB each
#define AT_A   (AT_V + NV * 4)                 // 2 x 128*40*4 = 40960
#define AT_B   (AT_A + 2 * 20480)              // 2 x 256*40*4 = 81920
#define AT_SC  (AT_B + 2 * 40960)
#define AT_SMEM (AT_SC + 3 * 128 * 4)          // 189952 B

__global__ __launch_bounds__(512, 1) void k_attn(float* __restrict__ out_alpha) {
    extern __shared__ char sm[];
    float*    sU = (float*)(sm + AT_U);
    float*    sV = (float*)(sm + AT_V);
    uint32_t* sAs[2] = { (uint32_t*)(sm + AT_A), (uint32_t*)(sm + AT_A + 20480) };
    float* sc  = (float*)(sm + AT_SC);
    float* sd  = sc + 128;
    float* stt = sd + 128;

    const int tid = threadIdx.x;
    const int wid = tid >> 5, lane = tid & 31;
    const int wm = wid >> 2, wn = wid & 3;        // 4 x 4 warps, tile 32x64
    const int kh = blockIdx.x, rt = blockIdx.y;
    const int r0 = rt * 128;
    const int br = tid >> 2, gA8 = (tid & 3) * 8; // A-build: group (tid&3), 8 words
    const int kq0 = (tid & 3) * 16;
    const bool wA = (out_alpha != nullptr);
    const uint32_t sbB = smem_u32(sm + AT_B);
    const unsigned* bmPtr = &g_bm[(size_t)(r0 + br) * 256 + (size_t)kh * 128];

    // preload u, v, row constants
#pragma unroll
    for (int q = 0; q < 4; q++) {
        int idx = (q * 512 + tid) * 4;
        *(float4*)&sU[idx] = *(const float4*)&g_u[idx];
        *(float4*)&sV[idx] = *(const float4*)&g_v[idx];
    }
    if (tid < 128) {
        sc[tid]  = g_c[r0 + tid];
        sd[tid]  = g_d[r0 + tid];
        stt[tid] = 1.f / g_u[r0 + tid];
    }

    float acc[2][8][4];
#pragma unroll
    for (int mt = 0; mt < 2; mt++)
#pragma unroll
        for (int nb = 0; nb < 8; nb++)
#pragma unroll
            for (int q = 0; q < 4; q++) acc[mt][nb][q] = 0.f;
    __syncthreads();

    // B tile: 256 n-rows x 32 words (permuted already in gmem), pitch 40
    auto cp_B = [&](int it, int s) {
        const int kb = kh * (NV / 2) + it * 64;
        uint32_t base = sbB + s * 40960;
#pragma unroll
        for (int q = 0; q < 4; q++) {
            int idx = q * 512 + tid;
            int n = idx >> 3, seg = idx & 7;      // seg: 8 fp16 (16B)
            cp_async16(base + (n * 40 + seg * 4) * 4,
                       (const char*)g_WhT16 + ((size_t)n * NV + kb + seg * 8) * 2);
        }
    };
    // A tile: 128 rows x 32 words, pitch 40, permuted pairs + row-parity XOR.
    auto build_A = [&](int it, int s, uint2 w2) {
        const int kb = kh * (NV / 2) + it * 64;
        float ci = sc[br], di = sd[br], th = stt[br];
        uint32_t word = ((tid & 3) < 2) ? w2.x : w2.y;
        int sh = kq0 & 16;
        uint32_t* sA = sAs[s];
        const int xo = (br & 1) << 2;
#pragma unroll
        for (int half = 0; half < 2; half++) {
            // half 0: logical e 0..3 & 8..11 (words t=0,1,4,5)
            // half 1: logical e 4..7 & 12..15 (words t=2,3,6,7)
            int jlo = kq0 + half * 4;
            int jhi = kq0 + 8 + half * 4;
            float4 uL = *(const float4*)&sU[kb + jlo];
            float4 vL = *(const float4*)&sV[kb + jlo];
            float4 uH = *(const float4*)&sU[kb + jhi];
            float4 vH = *(const float4*)&sV[kb + jhi];
            const float ue[8] = {uL.x, uL.y, uL.z, uL.w, uH.x, uH.y, uH.z, uH.w};
            const float ve[8] = {vL.x, vL.y, vL.z, vL.w, vH.x, vH.y, vH.z, vH.w};
            float av[8];
#pragma unroll
            for (int e = 0; e < 4; e++) {
                bool bit = (word >> (sh + half * 4 + e)) & 1u;
                av[e] = bit ? ((ue[e] > th) ? ci * ue[e] : di * ve[e]) : 0.f;
            }
#pragma unroll
            for (int e = 4; e < 8; e++) {
                bool bit = (word >> (sh + 8 + half * 4 + (e - 4))) & 1u;
                av[e] = bit ? ((ue[e] > th) ? ci * ue[e] : di * ve[e]) : 0.f;
            }
            if (wA) {
                float* dst = &out_alpha[(size_t)(r0 + br) * NV + kb];
                *(float4*)(dst + jlo) = make_float4(av[0], av[1], av[2], av[3]);
                *(float4*)(dst + jhi) = make_float4(av[4], av[5], av[6], av[7]);
            }
            // words: tL = half*2+{0,1} (pairs av0-1, av2-3); tH = 4+half*2+{0,1}
            uint32_t W0 = h2pack(av[0], av[1]);   // t = 2*half
            uint32_t W1 = h2pack(av[2], av[3]);   // t = 2*half+1
            uint32_t W4 = h2pack(av[4], av[5]);   // t = 2*half+4
            uint32_t W5 = h2pack(av[6], av[7]);   // t = 2*half+5
            // permuted: t' = 2t (t<4), 2(t-4)+1 -> uint4 at (gA8 + 4*half) ^ xo
            *(uint4*)&sA[br * 40 + ((gA8 + 4 * half) ^ xo)] =
                make_uint4(W0, W4, W1, W5);
        }
    };
    auto do_mma = [&](int s) {
        uint32_t* sA = sAs[s];
        const uint32_t* sB = (const uint32_t*)(sm + AT_B + s * 40960);
#pragma unroll
        for (int kk = 0; kk < 4; kk++) {
            const int tA = kk * 8 + 2 * (lane & 3);
            uint32_t afr[2][4];
#pragma unroll
            for (int mt = 0; mt < 2; mt++) {
                int r = wm * 32 + mt * 16 + (lane >> 2);
                int off = tA ^ ((r & 1) << 2);
                uint2 p = *(const uint2*)&sA[r * 40 + off];
                uint2 q = *(const uint2*)&sA[(r + 8) * 40 + off];
                afr[mt][0] = p.x; afr[mt][1] = q.x;
                afr[mt][2] = p.y; afr[mt][3] = q.y;
            }
#pragma unroll
            for (int nb = 0; nb < 8; nb++) {
                int n = wn * 64 + nb * 8 + (lane >> 2);
                uint2 b = *(const uint2*)&sB[n * 40 + tA];
                uint32_t bfr[2] = { b.x, b.y };
                mma_f16(acc[0][nb], afr[0], bfr);
                mma_f16(acc[1][nb], afr[1], bfr);
            }
        }
    };

    // ---- prologue ----
    uint2 wcur = *(const uint2*)&bmPtr[0];
    cp_B(0, 0); CP_COMMIT();
    build_A(0, 0, wcur);
    wcur = *(const uint2*)&bmPtr[2];
    CP_WAIT0();
    __syncthreads();

#pragma unroll 1
    for (int it = 0; it < 64; it++) {
        uint2 wpre = make_uint2(0, 0);
        if (it + 2 < 64) wpre = *(const uint2*)&bmPtr[(it + 2) * 2];
        if (it + 1 < 64) cp_B(it + 1, (it + 1) & 1);   // stage idle this iter
        CP_COMMIT();
        do_mma(it & 1);
        if (it < 63) build_A(it + 1, (it + 1) & 1, wcur);
        wcur = wpre;
        CP_WAIT0();
        __syncthreads();
    }

    // ---- epilogue: split-K partials ----
#pragma unroll
    for (int mt = 0; mt < 2; mt++)
#pragma unroll
        for (int nb = 0; nb < 8; nb++) {
            int gr = r0 + wm * 32 + mt * 16 + (lane >> 2);
            int cl = wn * 64 + nb * 8 + (lane & 3) * 2;
            float* base = &g_part[((size_t)kh * NV + gr) * DV + cl];
            *(float2*)base            = make_float2(acc[mt][nb][0], acc[mt][nb][1]);
            *(float2*)(base + 8 * DV) = make_float2(acc[mt][nb][2], acc[mt][nb][3]);
        }
}

// ---------------------------------------------------------------------------
// Kernel 5: combine split-K partials + elu
// ---------------------------------------------------------------------------
__global__ __launch_bounds__(256) void k_combine(float* __restrict__ out_elu) {
    float* o = out_elu ? out_elu : g_elu_scratch;
    size_t i = ((size_t)blockIdx.x * 256 + threadIdx.x) * 4;
    float4 p0 = *(float4*)&g_part[i];
    float4 p1 = *(float4*)&g_part[(size_t)NV * DV + i];
    float4 r;
    r.x = elu_f(p0.x + p1.x);
    r.y = elu_f(p0.y + p1.y);
    r.z = elu_f(p0.z + p1.z);
    r.w = elu_f(p0.w + p1.w);
    *(float4*)&o[i] = r;
}

// ---------------------------------------------------------------------------
extern "C" void kernel_launch(void* const* d_in, const int* in_sizes, int n_in,
                              void* d_out, int out_size) {
    const float* h   = (const float*)d_in[0];
    const int*   adj = (const int*)d_in[1];
    const float* W   = (const float*)d_in[2];
    const float* a   = (const float*)d_in[3];
    float* out = (float*)d_out;

    const long long elu_n = (long long)NV * DV;
    const long long alp_n = (long long)NV * NV;
    float* out_elu;
    float* out_alpha;
    if ((long long)out_size >= elu_n + alp_n) { out_elu = out; out_alpha = out + elu_n; }
    else if ((long long)out_size == alp_n)    { out_elu = nullptr; out_alpha = out; }
    else                                      { out_elu = out; out_alpha = nullptr; }

    cudaFuncSetAttribute(k_wh_mma, cudaFuncAttributeMaxDynamicSharedMemorySize, WH_SMEM);
    cudaFuncSetAttribute(k_attn,   cudaFuncAttributeMaxDynamicSharedMemorySize, AT_SMEM);

    dim3 gW(NV / 128, 2);
    k_wh_mma<<<gW, 512, WH_SMEM>>>(h, W, a);
    k_f<<<NV / 8, 256>>>(h);
    k_prep<<<NV, 256>>>(adj);
    dim3 gA(2, NV / 128);
    k_attn<<<gA, 512, AT_SMEM>>>(out_alpha);
    k_combine<<<(unsigned)(elu_n / 4 / 256), 256>>>(out_elu);
}

// round 17
// speedup vs baseline: 1.1829x; 1.1829x over previous
#include <cuda_runtime.h>
#include <cuda_fp16.h>
#include <cstdint>
#include <math.h>

#define NV 8192
#define DV 256

// ---------------- device scratch (allocation-free rule) ----------------
__device__ __half   g_WhT16[DV * NV];   // Wh^T, fp16, [col][j] (B operand)
__device__ float    g_wa[DV];           // W @ a
__device__ float    g_u[NV];            // exp(f)
__device__ float    g_v[NV];            // exp(0.2 f)
__device__ float    g_c[NV];            // u/s
__device__ float    g_d[NV];            // v/s
__device__ unsigned g_bm[NV * 256];     // adjacency bitmask
__device__ float    g_part[2 * NV * DV];
__device__ float    g_elu_scratch[NV * DV];

__device__ __forceinline__ float elu_f(float x) { return x > 0.f ? x : expm1f(x); }
__device__ __forceinline__ uint32_t tf32r(float x) {
    uint32_t r; asm("cvt.rna.tf32.f32 %0, %1;" : "=r"(r) : "f"(x)); return r;
}
__device__ __forceinline__ void mma_tf32(float* d, const uint32_t* a, const uint32_t* b) {
    asm volatile("mma.sync.aligned.m16n8k8.row.col.f32.tf32.tf32.f32 "
        "{%0,%1,%2,%3},{%4,%5,%6,%7},{%8,%9},{%0,%1,%2,%3};"
        : "+f"(d[0]), "+f"(d[1]), "+f"(d[2]), "+f"(d[3])
        : "r"(a[0]), "r"(a[1]), "r"(a[2]), "r"(a[3]), "r"(b[0]), "r"(b[1]));
}
__device__ __forceinline__ void mma_f16(float* d, const uint32_t* a, const uint32_t* b) {
    asm volatile("mma.sync.aligned.m16n8k16.row.col.f32.f16.f16.f32 "
        "{%0,%1,%2,%3},{%4,%5,%6,%7},{%8,%9},{%0,%1,%2,%3};"
        : "+f"(d[0]), "+f"(d[1]), "+f"(d[2]), "+f"(d[3])
        : "r"(a[0]), "r"(a[1]), "r"(a[2]), "r"(a[3]), "r"(b[0]), "r"(b[1]));
}
__device__ __forceinline__ void ldsm_x4(uint32_t& r0, uint32_t& r1, uint32_t& r2,
                                        uint32_t& r3, uint32_t addr) {
    asm volatile("ldmatrix.sync.aligned.m8n8.x4.shared.b16 {%0,%1,%2,%3}, [%4];"
        : "=r"(r0), "=r"(r1), "=r"(r2), "=r"(r3) : "r"(addr));
}
__device__ __forceinline__ uint32_t smem_u32(const void* p) {
    uint32_t a;
    asm("{ .reg .u64 t; cvta.to.shared.u64 t, %1; cvt.u32.u64 %0, t; }" : "=r"(a) : "l"(p));
    return a;
}
__device__ __forceinline__ void cp_async16(uint32_t dst, const void* src) {
    asm volatile("cp.async.ca.shared.global [%0], [%1], 16;" :: "r"(dst), "l"(src));
}
#define CP_COMMIT() asm volatile("cp.async.commit_group;" ::: "memory")
#define CP_WAIT0()  asm volatile("cp.async.wait_group 0;" ::: "memory")
__device__ __forceinline__ uint32_t h2pack(float lo, float hi) {
    __half2 h = __floats2half2_rn(lo, hi);
    return *reinterpret_cast<uint32_t*>(&h);
}

// ---------------------------------------------------------------------------
// Kernel 1: Wh = h @ W via tf32 mma; epilogue writes fp16 Wh^T [col][j].
// Also computes wa = W@a in block (0,0). CTA = 128 x 128 (grid 64x2).
// ---------------------------------------------------------------------------
#define WH_SMEM (128 * 36 * 4 + 32 * 136 * 4)
__global__ __launch_bounds__(512) void k_wh_mma(const float* __restrict__ h,
                                                const float* __restrict__ W,
                                                const float* __restrict__ a) {
    extern __shared__ char sm[];
    uint32_t* sA = (uint32_t*)sm;
    float*    sB = (float*)(sm + 128 * 36 * 4);
    const int tid = threadIdx.x;
    const int wid = tid >> 5, lane = tid & 31;
    const int wm = wid >> 2, wn = wid & 3;
    const int r0 = blockIdx.x * 128;
    const int cb = blockIdx.y * 128;
    const int br = tid >> 2, kq = (tid & 3) * 8;

    if (blockIdx.x == 0 && blockIdx.y == 0 && tid < 256) {
        const float4* W4 = (const float4*)W;
        const float4* a4 = (const float4*)a;
        float s = 0.f;
#pragma unroll 8
        for (int j = 0; j < 64; j++) {
            float4 w = __ldg(&W4[tid * 64 + j]);
            float4 av = __ldg(&a4[j]);
            s += w.x * av.x + w.y * av.y + w.z * av.z + w.w * av.w;
        }
        g_wa[tid] = s;
    }

    float acc[2][4][4];
#pragma unroll
    for (int mt = 0; mt < 2; mt++)
#pragma unroll
        for (int nb = 0; nb < 4; nb++)
#pragma unroll
            for (int q = 0; q < 4; q++) acc[mt][nb][q] = 0.f;

    for (int c = 0; c < 8; c++) {
        const int kb = c * 32;
        {
            float4 h0 = __ldg((const float4*)&h[(size_t)(r0 + br) * DV + kb + kq]);
            float4 h1 = __ldg((const float4*)&h[(size_t)(r0 + br) * DV + kb + kq + 4]);
            *(uint4*)&sA[br * 36 + kq]     = make_uint4(tf32r(h0.x), tf32r(h0.y), tf32r(h0.z), tf32r(h0.w));
            *(uint4*)&sA[br * 36 + kq + 4] = make_uint4(tf32r(h1.x), tf32r(h1.y), tf32r(h1.z), tf32r(h1.w));
        }
#pragma unroll
        for (int q = 0; q < 2; q++) {
            int idx = q * 512 + tid;
            int row = idx >> 5, col = (idx & 31) << 2;
            float4 w = __ldg((const float4*)&W[(size_t)(kb + row) * DV + cb + col]);
            float4 t;
            t.x = __uint_as_float(tf32r(w.x)); t.y = __uint_as_float(tf32r(w.y));
            t.z = __uint_as_float(tf32r(w.z)); t.w = __uint_as_float(tf32r(w.w));
            *(float4*)&sB[row * 136 + col] = t;
        }
        __syncthreads();
#pragma unroll
        for (int kk = 0; kk < 4; kk++) {
            uint32_t afr[2][4];
#pragma unroll
            for (int mt = 0; mt < 2; mt++) {
                int r = wm * 32 + mt * 16 + (lane >> 2);
                int cc = kk * 8 + (lane & 3);
                afr[mt][0] = sA[r * 36 + cc];
                afr[mt][1] = sA[(r + 8) * 36 + cc];
                afr[mt][2] = sA[r * 36 + cc + 4];
                afr[mt][3] = sA[(r + 8) * 36 + cc + 4];
            }
#pragma unroll
            for (int nb = 0; nb < 4; nb++) {
                uint32_t bfr[2];
                int kr = kk * 8 + (lane & 3);
                int nc = wn * 32 + nb * 8 + (lane >> 2);
                bfr[0] = __float_as_uint(sB[kr * 136 + nc]);
                bfr[1] = __float_as_uint(sB[(kr + 4) * 136 + nc]);
                mma_tf32(acc[0][nb], afr[0], bfr);
                mma_tf32(acc[1][nb], afr[1], bfr);
            }
        }
        __syncthreads();
    }
#pragma unroll
    for (int mt = 0; mt < 2; mt++)
#pragma unroll
        for (int nb = 0; nb < 4; nb++) {
            int gr = r0 + wm * 32 + mt * 16 + (lane >> 2);
            int cl = cb + wn * 32 + nb * 8 + (lane & 3) * 2;
            g_WhT16[(size_t)cl * NV + gr]           = __float2half_rn(acc[mt][nb][0]);
            g_WhT16[(size_t)(cl + 1) * NV + gr]     = __float2half_rn(acc[mt][nb][1]);
            g_WhT16[(size_t)cl * NV + gr + 8]       = __float2half_rn(acc[mt][nb][2]);
            g_WhT16[(size_t)(cl + 1) * NV + gr + 8] = __float2half_rn(acc[mt][nb][3]);
        }
}

// ---------------------------------------------------------------------------
// Kernel 2: f = h @ wa (exact); u = exp(f), v = exp(0.2 f)
// ---------------------------------------------------------------------------
__global__ __launch_bounds__(256) void k_f(const float* __restrict__ h) {
    const int wid = threadIdx.x >> 5, lane = threadIdx.x & 31;
    const int row = blockIdx.x * 8 + wid;
    float s = 0.f;
#pragma unroll
    for (int i = 0; i < 2; i++) {
        float4 w = __ldg((const float4*)&h[(size_t)row * DV + lane * 8 + i * 4]);
        float4 av = __ldg((const float4*)&g_wa[lane * 8 + i * 4]);
        s += w.x * av.x + w.y * av.y + w.z * av.z + w.w * av.w;
    }
#pragma unroll
    for (int m = 16; m; m >>= 1) s += __shfl_xor_sync(0xffffffffu, s, m);
    if (lane == 0) {
        g_u[row] = __expf(s);
        g_v[row] = __expf(0.2f * s);
    }
}

// ---------------------------------------------------------------------------
// Kernel 3: bitmask + rowsum (separable). One block per row.
// ---------------------------------------------------------------------------
__global__ __launch_bounds__(256) void k_prep(const int* __restrict__ adj) {
    const int row = blockIdx.x;
    const int wid = threadIdx.x >> 5, lane = threadIdx.x & 31;
    const float ui = __ldg(&g_u[row]);
    const float vi = __ldg(&g_v[row]);
    const float th = 1.f / ui;
    const int4* ar = (const int4*)(adj + (size_t)row * NV);
    const float4* u4p = (const float4*)g_u;
    const float4* v4p = (const float4*)g_v;

    float su = 0.f, sv = 0.f;
#pragma unroll
    for (int it = 0; it < 8; it++) {
        int idx4 = wid * 256 + it * 32 + lane;
        int4   ad = __ldg(&ar[idx4]);
        float4 u4 = __ldg(&u4p[idx4]);
        float4 v4 = __ldg(&v4p[idx4]);
        bool m0 = ad.x > 0, m1 = ad.y > 0, m2 = ad.z > 0, m3 = ad.w > 0;
        uint32_t nib = (m0 ? 1u : 0u) | (m1 ? 2u : 0u) | (m2 ? 4u : 0u) | (m3 ? 8u : 0u);
        bool p0 = u4.x > th, p1 = u4.y > th, p2 = u4.z > th, p3 = u4.w > th;
        su += (m0 && p0) ? u4.x : 0.f;  sv += (m0 && !p0) ? v4.x : 0.f;
        su += (m1 && p1) ? u4.y : 0.f;  sv += (m1 && !p1) ? v4.y : 0.f;
        su += (m2 && p2) ? u4.z : 0.f;  sv += (m2 && !p2) ? v4.z : 0.f;
        su += (m3 && p3) ? u4.w : 0.f;  sv += (m3 && !p3) ? v4.w : 0.f;
        uint32_t o = __shfl_xor_sync(0xffffffffu, nib, 1);
        uint32_t byt = (lane & 1) ? (o | (nib << 4)) : (nib | (o << 4));
        o = __shfl_xor_sync(0xffffffffu, byt, 2);
        uint32_t hlf = (lane & 2) ? (o | (byt << 8)) : (byt | (o << 8));
        o = __shfl_xor_sync(0xffffffffu, hlf, 4);
        uint32_t wrd = (lane & 4) ? (o | (hlf << 16)) : (hlf | (o << 16));
        if ((lane & 7) == 0)
            g_bm[(size_t)row * 256 + wid * 32 + it * 4 + (lane >> 3)] = wrd;
    }
#pragma unroll
    for (int m = 16; m; m >>= 1) {
        su += __shfl_xor_sync(0xffffffffu, su, m);
        sv += __shfl_xor_sync(0xffffffffu, sv, m);
    }
    __shared__ float ssu[8], ssv[8];
    if (lane == 0) { ssu[wid] = su; ssv[wid] = sv; }
    __syncthreads();
    if (threadIdx.x == 0) {
        float tu = 0.f, tv = 0.f;
#pragma unroll
        for (int i = 0; i < 8; i++) { tu += ssu[i]; tv += ssv[i]; }
        float s = ui * tu + vi * tv;
        g_c[row] = ui / s;
        g_d[row] = vi / s;
    }
}

// ---------------------------------------------------------------------------
// Kernel 4: h' = alpha @ Wh via fp16 m16n8k16 + ldmatrix fragment feeds.
// K=64/barrier, 64 iters. 512 threads, 16 warps (4x4), warp tile 32x64,
// CTA 128 x 256, split-K=2. Tiles pitch-36 (LDSM conflict-free: 36%32=4).
// ---------------------------------------------------------------------------
#define AT_U   0
#define AT_V   (AT_U + NV * 4)                 // 32 KB each
#define AT_A   (AT_V + NV * 4)                 // 2 x 128*36*4 = 36864
#define AT_B   (AT_A + 2 * 18432)              // 2 x 256*36*4 = 73728
#define AT_SC  (AT_B + 2 * 36864)
#define AT_SMEM (AT_SC + 3 * 128 * 4)          // 178688 B

__global__ __launch_bounds__(512, 1) void k_attn(float* __restrict__ out_alpha) {
    extern __shared__ char sm[];
    float*    sU = (float*)(sm + AT_U);
    float*    sV = (float*)(sm + AT_V);
    uint32_t* sAs[2] = { (uint32_t*)(sm + AT_A), (uint32_t*)(sm + AT_A + 18432) };
    float* sc  = (float*)(sm + AT_SC);
    float* sd  = sc + 128;
    float* stt = sd + 128;

    const int tid = threadIdx.x;
    const int wid = tid >> 5, lane = tid & 31;
    const int wm = wid >> 2, wn = wid & 3;        // 4 x 4 warps, tile 32x64
    const int kh = blockIdx.x, rt = blockIdx.y;
    const int r0 = rt * 128;
    const int br = tid >> 2, kq0 = (tid & 3) * 16; // A-build: 16 els/thread
    const bool wA = (out_alpha != nullptr);
    const uint32_t sbA = smem_u32(sm + AT_A);
    const uint32_t sbB = smem_u32(sm + AT_B);
    const unsigned* bmPtr = &g_bm[(size_t)(r0 + br) * 256 + (size_t)kh * 128];

    // ldmatrix per-lane base offsets (loop-invariant)
    // A x4: m0=[m0..7,k lo] m1=[m8..15,k lo] m2=[m0..7,k hi] m3=[m8..15,k hi]
    const int aRow = wm * 32 + ((lane >> 3) & 1) * 8 + (lane & 7);
    const int aKw  = ((lane >> 4) & 1) * 4;
    // B x4: m0=[n0..7,k lo] m1=[n0..7,k hi] m2=[n8..15,k lo] m3=[n8..15,k hi]
    const int bN   = wn * 64 + ((lane >> 4) & 1) * 8 + (lane & 7);
    const int bKw  = ((lane >> 3) & 1) * 4;

    // preload u, v, row constants
#pragma unroll
    for (int q = 0; q < 4; q++) {
        int idx = (q * 512 + tid) * 4;
        *(float4*)&sU[idx] = *(const float4*)&g_u[idx];
        *(float4*)&sV[idx] = *(const float4*)&g_v[idx];
    }
    if (tid < 128) {
        sc[tid]  = g_c[r0 + tid];
        sd[tid]  = g_d[r0 + tid];
        stt[tid] = 1.f / g_u[r0 + tid];
    }

    float acc[2][8][4];
#pragma unroll
    for (int mt = 0; mt < 2; mt++)
#pragma unroll
        for (int nb = 0; nb < 8; nb++)
#pragma unroll
            for (int q = 0; q < 4; q++) acc[mt][nb][q] = 0.f;
    __syncthreads();

    // B tile: 256 n-rows x 32 k-pair words, pitch 36
    auto cp_B = [&](int it, int s) {
        const int kb = kh * (NV / 2) + it * 64;
        uint32_t base = sbB + s * 36864;
#pragma unroll
        for (int q = 0; q < 4; q++) {
            int idx = q * 512 + tid;
            int n = idx >> 3, seg = idx & 7;      // seg: 8 fp16 (16B)
            cp_async16(base + (n * 36 + seg * 4) * 4,
                       (const char*)g_WhT16 + ((size_t)n * NV + kb + seg * 8) * 2);
        }
    };
    // A tile: 128 rows x 32 k-pair words, pitch 36. 16 alphas/thread.
    auto build_A = [&](int it, int s, uint2 w2) {
        const int kb = kh * (NV / 2) + it * 64;
        float ci = sc[br], di = sd[br], th = stt[br];
        uint32_t word = ((tid & 3) < 2) ? w2.x : w2.y;
        int sh = kq0 & 16;                        // bit base within word
        uint32_t* sA = sAs[s];
#pragma unroll
        for (int hf = 0; hf < 2; hf++) {          // two halves of 8
            int j = kq0 + hf * 8;
            float4 u0 = *(const float4*)&sU[kb + j];
            float4 u1 = *(const float4*)&sU[kb + j + 4];
            float4 v0 = *(const float4*)&sV[kb + j];
            float4 v1 = *(const float4*)&sV[kb + j + 4];
            const float ue[8] = {u0.x, u0.y, u0.z, u0.w, u1.x, u1.y, u1.z, u1.w};
            const float ve[8] = {v0.x, v0.y, v0.z, v0.w, v1.x, v1.y, v1.z, v1.w};
            float av[8];
#pragma unroll
            for (int e = 0; e < 8; e++) {
                bool bit = (word >> (sh + hf * 8 + e)) & 1u;
                av[e] = bit ? ((ue[e] > th) ? ci * ue[e] : di * ve[e]) : 0.f;
            }
            if (wA) {
                float* dst = &out_alpha[(size_t)(r0 + br) * NV + kb + j];
                *(float4*)dst       = make_float4(av[0], av[1], av[2], av[3]);
                *(float4*)(dst + 4) = make_float4(av[4], av[5], av[6], av[7]);
            }
            uint4 pw = make_uint4(h2pack(av[0], av[1]), h2pack(av[2], av[3]),
                                  h2pack(av[4], av[5]), h2pack(av[6], av[7]));
            *(uint4*)&sA[br * 36 + (j >> 1)] = pw;
        }
    };
    auto do_mma = [&](int s) {
        const uint32_t aBase = sbA + s * 18432 + (aRow * 36 + aKw) * 4;
        const uint32_t bBase = sbB + s * 36864 + (bN * 36 + bKw) * 4;
#pragma unroll
        for (int kk = 0; kk < 4; kk++) {
            uint32_t afr[2][4];
            ldsm_x4(afr[0][0], afr[0][1], afr[0][2], afr[0][3],
                    aBase + kk * 32);
            ldsm_x4(afr[1][0], afr[1][1], afr[1][2], afr[1][3],
                    aBase + 16 * 36 * 4 + kk * 32);
#pragma unroll
            for (int p = 0; p < 4; p++) {
                uint32_t b0, b1, b2, b3;
                ldsm_x4(b0, b1, b2, b3, bBase + p * 16 * 36 * 4 + kk * 32);
                uint32_t bf0[2] = { b0, b1 };
                uint32_t bf1[2] = { b2, b3 };
                mma_f16(acc[0][2 * p],     afr[0], bf0);
                mma_f16(acc[1][2 * p],     afr[1], bf0);
                mma_f16(acc[0][2 * p + 1], afr[0], bf1);
                mma_f16(acc[1][2 * p + 1], afr[1], bf1);
            }
        }
    };

    // ---- prologue: B(0) in flight; A(0) built; bm for it=1 prefetched ----
    uint2 wcur = *(const uint2*)&bmPtr[0];
    cp_B(0, 0); CP_COMMIT();
    build_A(0, 0, wcur);
    wcur = *(const uint2*)&bmPtr[2];
    CP_WAIT0();                                   // B(0) resident
    __syncthreads();

#pragma unroll 1
    for (int it = 0; it < 64; it++) {
        uint2 wpre = make_uint2(0, 0);
        if (it + 2 < 64) wpre = *(const uint2*)&bmPtr[(it + 2) * 2];
        if (it + 1 < 64) cp_B(it + 1, (it + 1) & 1);   // stage idle this iter
        CP_COMMIT();
        do_mma(it & 1);
        if (it < 63) build_A(it + 1, (it + 1) & 1, wcur);
        wcur = wpre;
        CP_WAIT0();                               // B(it+1) resident before barrier
        __syncthreads();
    }

    // ---- epilogue: split-K partials ----
#pragma unroll
    for (int mt = 0; mt < 2; mt++)
#pragma unroll
        for (int nb = 0; nb < 8; nb++) {
            int gr = r0 + wm * 32 + mt * 16 + (lane >> 2);
            int cl = wn * 64 + nb * 8 + (lane & 3) * 2;
            float* base = &g_part[((size_t)kh * NV + gr) * DV + cl];
            *(float2*)base            = make_float2(acc[mt][nb][0], acc[mt][nb][1]);
            *(float2*)(base + 8 * DV) = make_float2(acc[mt][nb][2], acc[mt][nb][3]);
        }
}

// ---------------------------------------------------------------------------
// Kernel 5: combine split-K partials + elu
// ---------------------------------------------------------------------------
__global__ __launch_bounds__(256) void k_combine(float* __restrict__ out_elu) {
    float* o = out_elu ? out_elu : g_elu_scratch;
    size_t i = ((size_t)blockIdx.x * 256 + threadIdx.x) * 4;
    float4 p0 = *(float4*)&g_part[i];
    float4 p1 = *(float4*)&g_part[(size_t)NV * DV + i];
    float4 r;
    r.x = elu_f(p0.x + p1.x);
    r.y = elu_f(p0.y + p1.y);
    r.z = elu_f(p0.z + p1.z);
    r.w = elu_f(p0.w + p1.w);
    *(float4*)&o[i] = r;
}

// ---------------------------------------------------------------------------
extern "C" void kernel_launch(void* const* d_in, const int* in_sizes, int n_in,
                              void* d_out, int out_size) {
    const float* h   = (const float*)d_in[0];
    const int*   adj = (const int*)d_in[1];
    const float* W   = (const float*)d_in[2];
    const float* a   = (const float*)d_in[3];
    float* out = (float*)d_out;

    const long long elu_n = (long long)NV * DV;
    const long long alp_n = (long long)NV * NV;
    float* out_elu;
    float* out_alpha;
    if ((long long)out_size >= elu_n + alp_n) { out_elu = out; out_alpha = out + elu_n; }
    else if ((long long)out_size == alp_n)    { out_elu = nullptr; out_alpha = out; }
    else                                      { out_elu = out; out_alpha = nullptr; }

    cudaFuncSetAttribute(k_wh_mma, cudaFuncAttributeMaxDynamicSharedMemorySize, WH_SMEM);
    cudaFuncSetAttribute(k_attn,   cudaFuncAttributeMaxDynamicSharedMemorySize, AT_SMEM);

    dim3 gW(NV / 128, 2);
    k_wh_mma<<<gW, 512, WH_SMEM>>>(h, W, a);
    k_f<<<NV / 8, 256>>>(h);
    k_prep<<<NV, 256>>>(adj);
    dim3 gA(2, NV / 128);
    k_attn<<<gA, 512, AT_SMEM>>>(out_alpha);
    k_combine<<<(unsigned)(elu_n / 4 / 256), 256>>>(out_elu);
}